// round 13
// baseline (speedup 1.0000x reference)
#include <cuda_runtime.h>
#include <cuda_fp16.h>
#include <math.h>
#include <stdint.h>

// ---------------- problem constants ----------------
#define LNUM 12
#define E 1024
#define H 16
#define T 512
#define BATCH 8
#define VOCAB 512
#define FF 4096
#define D 64
#define BT (BATCH*T)   // 4096

// ---------------- persistent device scratch ----------------
__device__ float  g_h [BT*E];
__device__ __half g_xn[BT*E];            // half, k-permuted
__device__ __half g_q [BT*E];            // half, D-permuted per head
__device__ __half g_k [BT*E];            // half, D-permuted per head
__device__ __half g_v [BT*E];            // half, plain
__device__ __half g_y [BT*E];            // half, k-permuted
__device__ __half g_ff[(size_t)BT*FF];   // half, k-permuted
// transposed (K-major, k-permuted) fp16 weights
__device__ __half g_WqT [(size_t)LNUM*E*E];
__device__ __half g_WkT [(size_t)LNUM*E*E];
__device__ __half g_WvT [(size_t)LNUM*E*E];
__device__ __half g_WpT [(size_t)LNUM*E*E];
__device__ __half g_Wf1T[(size_t)LNUM*E*FF];
__device__ __half g_Wf2T[(size_t)LNUM*FF*E];
__device__ __half g_headT[(size_t)E*VOCAB];

// ---------------- helpers ----------------
__device__ __forceinline__ uint32_t smem_u32(const void* p) {
    uint32_t a;
    asm("{ .reg .u64 t; cvta.to.shared.u64 t, %1; cvt.u32.u64 %0, t; }" : "=r"(a) : "l"(p));
    return a;
}
__device__ __forceinline__ void cp16(uint32_t saddr, const void* g) {
    asm volatile("cp.async.cg.shared.global [%0], [%1], 16;" :: "r"(saddr), "l"(g));
}
__device__ __forceinline__ void cp_commit() {
    asm volatile("cp.async.commit_group;" ::: "memory");
}
template<int N>
__device__ __forceinline__ void cp_wait() {
    asm volatile("cp.async.wait_group %0;" :: "n"(N) : "memory");
}
__device__ __forceinline__ void mma_f16(float* d, uint32_t a0, uint32_t a1, uint32_t a2,
                                        uint32_t a3, uint32_t b0, uint32_t b1) {
    asm volatile("mma.sync.aligned.m16n8k16.row.col.f32.f16.f16.f32 "
        "{%0,%1,%2,%3}, {%4,%5,%6,%7}, {%8,%9}, {%0,%1,%2,%3};"
        : "+f"(d[0]), "+f"(d[1]), "+f"(d[2]), "+f"(d[3])
        : "r"(a0), "r"(a1), "r"(a2), "r"(a3), "r"(b0), "r"(b1));
}
__device__ __forceinline__ int perm8(int w) {
    return (w & ~7) | ((w & 3) << 1) | ((w >> 2) & 1);
}
__device__ __forceinline__ int permh(int k) {
    return perm8(k >> 1) * 2 + (k & 1);
}

// ---------------- embedding ----------------
__global__ void embed_kernel(const int* __restrict__ x,
                             const float* __restrict__ tok,
                             const float* __restrict__ pos,
                             float* __restrict__ h)
{
    int idx = blockIdx.x * blockDim.x + threadIdx.x;
    if (idx >= BT*E) return;
    int row = idx >> 10;
    int e   = idx & (E-1);
    int t   = row & (T-1);
    h[idx] = tok[(size_t)x[row]*E + e] + pos[(size_t)t*E + e];
}

// ---------------- layernorm (fp16 k-permuted output) ----------------
__global__ __launch_bounds__(256) void ln_kernel(const float* __restrict__ in,
                                                 __half* __restrict__ out,
                                                 const float* __restrict__ gamma,
                                                 const float* __restrict__ beta)
{
    int row = blockIdx.x;
    const float* xr = in + (size_t)row * E;
    float s = 0.f, ss = 0.f;
    for (int i = threadIdx.x; i < E; i += 256) {
        float v = xr[i]; s += v; ss += v * v;
    }
    #pragma unroll
    for (int o = 16; o > 0; o >>= 1) {
        s  += __shfl_xor_sync(0xffffffffu, s,  o);
        ss += __shfl_xor_sync(0xffffffffu, ss, o);
    }
    __shared__ float sred[8], ssred[8];
    int w = threadIdx.x >> 5;
    if ((threadIdx.x & 31) == 0) { sred[w] = s; ssred[w] = ss; }
    __syncthreads();
    if (threadIdx.x < 32) {
        s  = (threadIdx.x < 8) ? sred [threadIdx.x] : 0.f;
        ss = (threadIdx.x < 8) ? ssred[threadIdx.x] : 0.f;
        #pragma unroll
        for (int o = 4; o > 0; o >>= 1) {
            s  += __shfl_xor_sync(0xffffffffu, s,  o);
            ss += __shfl_xor_sync(0xffffffffu, ss, o);
        }
        if (threadIdx.x == 0) { sred[0] = s; ssred[0] = ss; }
    }
    __syncthreads();
    float mu   = sred[0] * (1.f / E);
    float var  = ssred[0] * (1.f / E) - mu * mu;
    float rstd = rsqrtf(var + 1e-5f);
    __half* orow = out + (size_t)row * E;
    for (int i = threadIdx.x; i < E; i += 256)
        orow[permh(i)] = __float2half_rn((xr[i] - mu) * rstd * gamma[i] + beta[i]);
}

// ---------------- weight transpose ([R,C] fp32 -> [C,R] fp16, k-permuted) --------
__global__ __launch_bounds__(256) void transpose_h(const float* __restrict__ in,
                                                   __half* __restrict__ out, int R, int C)
{
    __shared__ float tile[32][33];
    size_t mat = (size_t)blockIdx.z * R * C;
    int c0 = blockIdx.x * 32, r0 = blockIdx.y * 32;
    #pragma unroll
    for (int j = threadIdx.y; j < 32; j += 8)
        tile[j][threadIdx.x] = in[mat + (size_t)(r0 + j) * C + c0 + threadIdx.x];
    __syncthreads();
    int pk = r0 + permh((int)threadIdx.x);
    #pragma unroll
    for (int j = threadIdx.y; j < 32; j += 8)
        out[mat + (size_t)(c0 + j) * R + pk] = __float2half_rn(tile[threadIdx.x][j]);
}

// ---------------- fp16 mma GEMM: 128x128 tile, 2 CTAs/SM, warp 32x64 --------------
// OUT: 0 = fp32 plain, 1 = fp16 k-permuted, 2 = fp16 plain
#define EPI_BIAS 0
#define EPI_GELU 1
#define EPI_RES  2
#define TKh 64
#define ROWW 40
#define S2_AW (128*ROWW)              // A words/stage = 5120
#define S2_W  (2*S2_AW)               // words/stage (A+B) = 10240
#define S2_B  (S2_W*4)                // 40960 bytes/stage
#define GSM_BYTES (2*S2_B)            // 81920 bytes

template<int EPI, int OUT>
__global__ __launch_bounds__(256, 2) void gemm_mma(int M, int N, int K,
    const __half* __restrict__ A, const __half* __restrict__ Bt,
    const float* __restrict__ bias, const float* __restrict__ res,
    void* __restrict__ Cv)
{
    extern __shared__ uint32_t smw[];
    const uint32_t sbase = smem_u32(smw);
    const int tid  = threadIdx.x;
    const int wid  = tid >> 5, lane = tid & 31;
    const int wm   = wid & 3, wn = wid >> 2;      // 4m x 2n warps, warp tile 32x64
    const int g    = lane >> 2, c = lane & 3;

    const size_t m0 = (size_t)blockIdx.y * 128;
    const int    n0 = blockIdx.x * 128;
    const int    nK = K / TKh;

    const int ldrow = tid >> 1;                   // 0..127
    const int ldch  = (tid & 1) * 4;              // chunk base 0 / 4

    auto load_tiles = [&](int kt, int st) {
        const int k0 = kt * TKh;
        const uint32_t sA = sbase + st*S2_B;
        const uint32_t sB = sA + S2_AW*4;
        const __half* Ag = A  + (m0 + ldrow) * K + k0 + ldch*8;
        const __half* Bg = Bt + (size_t)(n0 + ldrow) * K + k0 + ldch*8;
        #pragma unroll
        for (int i = 0; i < 4; i++) {
            cp16(sA + ldrow*160 + (ldch + i)*16, Ag + i*8);
            cp16(sB + ldrow*160 + (ldch + i)*16, Bg + i*8);
        }
        cp_commit();
    };

    float acc[2][8][4];
    #pragma unroll
    for (int mf = 0; mf < 2; mf++)
        #pragma unroll
        for (int nf = 0; nf < 8; nf++)
            #pragma unroll
            for (int i = 0; i < 4; i++) acc[mf][nf][i] = 0.f;

    load_tiles(0, 0);

    for (int kt = 0; kt < nK; kt++) {
        const int st = kt & 1;
        if (kt + 1 < nK) { load_tiles(kt + 1, st ^ 1); cp_wait<1>(); }
        else             { cp_wait<0>(); }
        __syncthreads();

        const uint32_t* as = smw + st*S2_W;
        const uint32_t* bs = as + S2_AW;

        // A-fragments register double-buffered; B loaded per k-step
        uint2 af[2][4];
        {
            const int kw = 2*c;
            #pragma unroll
            for (int mf = 0; mf < 2; mf++) {
                int r = wm*32 + mf*16 + g;
                af[0][2*mf]   = *(const uint2*)&as[ r      * ROWW + kw];
                af[0][2*mf+1] = *(const uint2*)&as[(r + 8) * ROWW + kw];
            }
        }
        #pragma unroll
        for (int ks = 0; ks < 4; ks++) {
            const int cur = ks & 1, nxt = cur ^ 1;
            uint2 bf[8];
            #pragma unroll
            for (int nf = 0; nf < 8; nf++)
                bf[nf] = *(const uint2*)&bs[(wn*64 + nf*8 + g) * ROWW + ks*8 + 2*c];
            if (ks < 3) {
                const int kw = (ks + 1)*8 + 2*c;
                #pragma unroll
                for (int mf = 0; mf < 2; mf++) {
                    int r = wm*32 + mf*16 + g;
                    af[nxt][2*mf]   = *(const uint2*)&as[ r      * ROWW + kw];
                    af[nxt][2*mf+1] = *(const uint2*)&as[(r + 8) * ROWW + kw];
                }
            }
            #pragma unroll
            for (int mf = 0; mf < 2; mf++)
                #pragma unroll
                for (int nf = 0; nf < 8; nf++)
                    mma_f16(acc[mf][nf],
                            af[cur][2*mf].x, af[cur][2*mf+1].x,
                            af[cur][2*mf].y, af[cur][2*mf+1].y,
                            bf[nf].x, bf[nf].y);
        }
        __syncthreads();
    }

    // epilogue
    #pragma unroll
    for (int mf = 0; mf < 2; mf++) {
        size_t r = m0 + wm*32 + mf*16 + g;
        #pragma unroll
        for (int nf = 0; nf < 8; nf++) {
            int col = n0 + wn*64 + nf*8 + c*2;
            float v0 = acc[mf][nf][0], v1 = acc[mf][nf][1];
            float v2 = acc[mf][nf][2], v3 = acc[mf][nf][3];
            if (bias) {
                float bb0 = bias[col], bb1 = bias[col+1];
                v0 += bb0; v1 += bb1; v2 += bb0; v3 += bb1;
            }
            if (EPI == EPI_GELU) {
                v0 = 0.5f*v0*(1.f + erff(v0*0.70710678118654752f));
                v1 = 0.5f*v1*(1.f + erff(v1*0.70710678118654752f));
                v2 = 0.5f*v2*(1.f + erff(v2*0.70710678118654752f));
                v3 = 0.5f*v3*(1.f + erff(v3*0.70710678118654752f));
            }
            if (EPI == EPI_RES) {
                const float* resp = res + r*N + col;
                float2 r0 = *(const float2*)resp;
                float2 r1 = *(const float2*)(resp + 8*N);
                v0 += r0.x; v1 += r0.y; v2 += r1.x; v3 += r1.y;
            }
            if (OUT == 1) {          // half, k-permuted
                __half* C = (__half*)Cv;
                int p0 = permh(col), p1 = permh(col + 1);
                C[r*N + p0]     = __float2half_rn(v0);
                C[r*N + p1]     = __float2half_rn(v1);
                C[(r+8)*N + p0] = __float2half_rn(v2);
                C[(r+8)*N + p1] = __float2half_rn(v3);
            } else if (OUT == 2) {   // half, plain
                __half* C = (__half*)Cv;
                *(__half2*)(C + r*N + col)     = __floats2half2_rn(v0, v1);
                *(__half2*)(C + (r+8)*N + col) = __floats2half2_rn(v2, v3);
            } else {                 // fp32
                float* C = (float*)Cv;
                float2 o0 = {v0, v1}, o1 = {v2, v3};
                *(float2*)(C + r*N + col)     = o0;
                *(float2*)(C + (r+8)*N + col) = o1;
            }
        }
    }
}

// ---------------- tensor-core flash attention (unchanged from R12) ----------------
__global__ __launch_bounds__(128) void attn_kernel(const __half* __restrict__ Qh,
                                                   const __half* __restrict__ Kh,
                                                   const __half* __restrict__ Vh,
                                                   __half* __restrict__ Y)
{
    __shared__ __align__(16) uint32_t sQ[64*ROWW];
    __shared__ __align__(16) uint32_t sK[64*ROWW];
    __shared__ __align__(16) uint32_t sVt[64*ROWW];

    const int bh = blockIdx.y;
    const int b  = bh >> 4;
    const int h  = bh & 15;
    const int qt = blockIdx.x;
    const int tid  = threadIdx.x;
    const int wid  = tid >> 5, lane = tid & 31;
    const int g    = lane >> 2, c = lane & 3;

    {
        int r2 = tid >> 1, wc = tid & 1;
        const uint4* qg = (const uint4*)(Qh + (size_t)(b*T + qt*64 + r2)*E + h*64 + wc*32);
        uint4* sq4 = (uint4*)(sQ + r2*ROWW + wc*16);
        sq4[0] = qg[0]; sq4[1] = qg[1]; sq4[2] = qg[2]; sq4[3] = qg[3];
    }
    __syncthreads();

    uint2 aq[4][2];
    {
        int qr = wid*16 + g;
        #pragma unroll
        for (int ks = 0; ks < 4; ks++) {
            aq[ks][0] = *(const uint2*)&sQ[ qr      * ROWW + ks*8 + 2*c];
            aq[ks][1] = *(const uint2*)&sQ[(qr + 8) * ROWW + ks*8 + 2*c];
        }
    }

    float o[8][4];
    #pragma unroll
    for (int dt = 0; dt < 8; dt++)
        #pragma unroll
        for (int i = 0; i < 4; i++) o[dt][i] = 0.f;
    float m0 = -INFINITY, m1 = -INFINITY, l0 = 0.f, l1 = 0.f;

    for (int kt = 0; kt <= qt; kt++) {
        __syncthreads();
        {
            int r2 = tid >> 1, wc = tid & 1;
            const uint4* kg = (const uint4*)(Kh + (size_t)(b*T + kt*64 + r2)*E + h*64 + wc*32);
            uint4* sk4 = (uint4*)(sK + r2*ROWW + wc*16);
            sk4[0] = kg[0]; sk4[1] = kg[1]; sk4[2] = kg[2]; sk4[3] = kg[3];
        }
        {
            int key = tid >> 1, dbase = (tid & 1) * 32;
            const uint4* vg = (const uint4*)(Vh + (size_t)(b*T + kt*64 + key)*E + h*64 + dbase);
            __half* vt = (__half*)sVt;
            int pk = permh(key);
            #pragma unroll
            for (int j = 0; j < 4; j++) {
                uint4 v = vg[j];
                const __half* hh = (const __half*)&v;
                #pragma unroll
                for (int i = 0; i < 8; i++)
                    vt[(dbase + j*8 + i)*(2*ROWW) + pk] = hh[i];
            }
        }
        __syncthreads();

        float s[8][4];
        #pragma unroll
        for (int nt = 0; nt < 8; nt++) {
            s[nt][0] = s[nt][1] = s[nt][2] = s[nt][3] = 0.f;
            #pragma unroll
            for (int ks = 0; ks < 4; ks++) {
                uint2 bk = *(const uint2*)&sK[(nt*8 + g) * ROWW + ks*8 + 2*c];
                mma_f16(s[nt], aq[ks][0].x, aq[ks][1].x, aq[ks][0].y, aq[ks][1].y,
                        bk.x, bk.y);
            }
        }

        const int wr0 = wid*16 + g, wr1 = wr0 + 8;
        float mx0 = -INFINITY, mx1 = -INFINITY;
        #pragma unroll
        for (int nt = 0; nt < 8; nt++) {
            #pragma unroll
            for (int i = 0; i < 4; i++) s[nt][i] *= 0.125f;
            if (kt == qt) {
                int cl = nt*8 + 2*c;
                if (cl     > wr0) s[nt][0] = -INFINITY;
                if (cl + 1 > wr0) s[nt][1] = -INFINITY;
                if (cl     > wr1) s[nt][2] = -INFINITY;
                if (cl + 1 > wr1) s[nt][3] = -INFINITY;
            }
            mx0 = fmaxf(mx0, fmaxf(s[nt][0], s[nt][1]));
            mx1 = fmaxf(mx1, fmaxf(s[nt][2], s[nt][3]));
        }
        mx0 = fmaxf(mx0, __shfl_xor_sync(0xffffffffu, mx0, 1));
        mx0 = fmaxf(mx0, __shfl_xor_sync(0xffffffffu, mx0, 2));
        mx1 = fmaxf(mx1, __shfl_xor_sync(0xffffffffu, mx1, 1));
        mx1 = fmaxf(mx1, __shfl_xor_sync(0xffffffffu, mx1, 2));

        float nm0 = fmaxf(m0, mx0), nm1 = fmaxf(m1, mx1);
        float f0 = __expf(m0 - nm0), f1 = __expf(m1 - nm1);
        m0 = nm0; m1 = nm1;

        float sum0 = 0.f, sum1 = 0.f;
        uint32_t ph[8][2];
        #pragma unroll
        for (int nt = 0; nt < 8; nt++) {
            float p0 = __expf(s[nt][0] - m0);
            float p1 = __expf(s[nt][1] - m0);
            float p2 = __expf(s[nt][2] - m1);
            float p3 = __expf(s[nt][3] - m1);
            sum0 += p0 + p1; sum1 += p2 + p3;
            __half2 h01 = __floats2half2_rn(p0, p1);
            __half2 h23 = __floats2half2_rn(p2, p3);
            ph[nt][0] = *(uint32_t*)&h01;
            ph[nt][1] = *(uint32_t*)&h23;
        }
        sum0 += __shfl_xor_sync(0xffffffffu, sum0, 1);
        sum0 += __shfl_xor_sync(0xffffffffu, sum0, 2);
        sum1 += __shfl_xor_sync(0xffffffffu, sum1, 1);
        sum1 += __shfl_xor_sync(0xffffffffu, sum1, 2);
        l0 = l0*f0 + sum0;
        l1 = l1*f1 + sum1;

        #pragma unroll
        for (int dt = 0; dt < 8; dt++) {
            o[dt][0] *= f0; o[dt][1] *= f0;
            o[dt][2] *= f1; o[dt][3] *= f1;
            #pragma unroll
            for (int kp = 0; kp < 4; kp++) {
                uint2 bv = *(const uint2*)&sVt[(dt*8 + g) * ROWW + kp*8 + 2*c];
                mma_f16(o[dt], ph[2*kp][0], ph[2*kp][1], ph[2*kp+1][0], ph[2*kp+1][1],
                        bv.x, bv.y);
            }
        }
    }

    float i0 = 1.f / l0, i1 = 1.f / l1;
    size_t row0 = (size_t)(b*T + qt*64 + wid*16 + g);
    size_t row1 = row0 + 8;
    #pragma unroll
    for (int dt = 0; dt < 8; dt++) {
        int gw = h*32 + dt*4 + c;
        int pw = perm8(gw);
        *(__half2*)(Y + row0*E + pw*2) = __floats2half2_rn(o[dt][0]*i0, o[dt][1]*i0);
        *(__half2*)(Y + row1*E + pw*2) = __floats2half2_rn(o[dt][2]*i1, o[dt][3]*i1);
    }
}

// ---------------- host orchestration ----------------
extern "C" void kernel_launch(void* const* d_in, const int* in_sizes, int n_in,
                              void* d_out, int out_size)
{
    (void)in_sizes; (void)n_in; (void)out_size;
    const int*   x     = (const int*)  d_in[0];
    const float* tok   = (const float*)d_in[2];
    const float* pos   = (const float*)d_in[3];
    const float* ln1_g = (const float*)d_in[4];
    const float* ln1_b = (const float*)d_in[5];
    const float* Wq    = (const float*)d_in[6];
    const float* bq    = (const float*)d_in[7];
    const float* Wk    = (const float*)d_in[8];
    const float* bk    = (const float*)d_in[9];
    const float* Wv    = (const float*)d_in[10];
    const float* bv    = (const float*)d_in[11];
    const float* Wp    = (const float*)d_in[12];
    const float* bp    = (const float*)d_in[13];
    const float* ln2_g = (const float*)d_in[14];
    const float* ln2_b = (const float*)d_in[15];
    const float* Wf1   = (const float*)d_in[16];
    const float* bf1   = (const float*)d_in[17];
    const float* Wf2   = (const float*)d_in[18];
    const float* bf2   = (const float*)d_in[19];
    const float* lnf_g = (const float*)d_in[20];
    const float* lnf_b = (const float*)d_in[21];
    const float* headw = (const float*)d_in[22];
    float* out = (float*)d_out;

    float *ph;
    __half *pxn, *pq, *pk, *pv, *py, *pff;
    __half *pWqT, *pWkT, *pWvT, *pWpT, *pWf1T, *pWf2T, *pHT;
    cudaGetSymbolAddress((void**)&ph,   g_h);
    cudaGetSymbolAddress((void**)&pxn,  g_xn);
    cudaGetSymbolAddress((void**)&pq,   g_q);
    cudaGetSymbolAddress((void**)&pk,   g_k);
    cudaGetSymbolAddress((void**)&pv,   g_v);
    cudaGetSymbolAddress((void**)&py,   g_y);
    cudaGetSymbolAddress((void**)&pff,  g_ff);
    cudaGetSymbolAddress((void**)&pWqT, g_WqT);
    cudaGetSymbolAddress((void**)&pWkT, g_WkT);
    cudaGetSymbolAddress((void**)&pWvT, g_WvT);
    cudaGetSymbolAddress((void**)&pWpT, g_WpT);
    cudaGetSymbolAddress((void**)&pWf1T, g_Wf1T);
    cudaGetSymbolAddress((void**)&pWf2T, g_Wf2T);
    cudaGetSymbolAddress((void**)&pHT,  g_headT);

    cudaFuncSetAttribute(gemm_mma<EPI_BIAS,1>, cudaFuncAttributeMaxDynamicSharedMemorySize, GSM_BYTES);
    cudaFuncSetAttribute(gemm_mma<EPI_BIAS,2>, cudaFuncAttributeMaxDynamicSharedMemorySize, GSM_BYTES);
    cudaFuncSetAttribute(gemm_mma<EPI_BIAS,0>, cudaFuncAttributeMaxDynamicSharedMemorySize, GSM_BYTES);
    cudaFuncSetAttribute(gemm_mma<EPI_GELU,1>, cudaFuncAttributeMaxDynamicSharedMemorySize, GSM_BYTES);
    cudaFuncSetAttribute(gemm_mma<EPI_RES ,0>, cudaFuncAttributeMaxDynamicSharedMemorySize, GSM_BYTES);

    dim3 tb(32, 8);
    dim3 gE(E/128,     BT/128);   // (8,32)  = 256 blocks
    dim3 gF(FF/128,    BT/128);   // (32,32) = 1024 blocks
    dim3 gV(VOCAB/128, BT/128);   // (4,32)  = 128 blocks
    dim3 gAtt(T/64, BATCH*H);

    transpose_h<<<dim3(E/32, E/32, LNUM), tb>>>(Wq, pWqT, E, E);            // 0
    embed_kernel<<<(BT*E + 255)/256, 256>>>(x, tok, pos, ph);               // 1
    ln_kernel<<<BT, 256>>>(ph, pxn, ln1_g, ln1_b);                          // 2
    gemm_mma<EPI_BIAS,1><<<gE, 256, GSM_BYTES>>>(BT, E, E, pxn, pWqT, bq, nullptr, pq);  // 3 <- profiled
    transpose_h<<<dim3(E/32,  E/32,  LNUM), tb>>>(Wk,  pWkT,  E,  E);
    transpose_h<<<dim3(E/32,  E/32,  LNUM), tb>>>(Wv,  pWvT,  E,  E);
    transpose_h<<<dim3(E/32,  E/32,  LNUM), tb>>>(Wp,  pWpT,  E,  E);
    transpose_h<<<dim3(FF/32, E/32,  LNUM), tb>>>(Wf1, pWf1T, E,  FF);
    transpose_h<<<dim3(E/32,  FF/32, LNUM), tb>>>(Wf2, pWf2T, FF, E);
    transpose_h<<<dim3(VOCAB/32, E/32, 1),  tb>>>(headw, pHT, E,  VOCAB);

    for (int l = 0; l < LNUM; l++) {
        const size_t wOff  = (size_t)l * E * E;
        const size_t f1Off = (size_t)l * E * FF;
        if (l > 0) {
            ln_kernel<<<BT, 256>>>(ph, pxn, ln1_g + l*E, ln1_b + l*E);
            gemm_mma<EPI_BIAS,1><<<gE, 256, GSM_BYTES>>>(BT, E, E, pxn, pWqT + wOff, bq + l*E, nullptr, pq);
        }
        gemm_mma<EPI_BIAS,1><<<gE, 256, GSM_BYTES>>>(BT, E, E, pxn, pWkT + wOff, bk + l*E, nullptr, pk);
        gemm_mma<EPI_BIAS,2><<<gE, 256, GSM_BYTES>>>(BT, E, E, pxn, pWvT + wOff, bv + l*E, nullptr, pv);
        attn_kernel<<<gAtt, 128>>>(pq, pk, pv, py);
        gemm_mma<EPI_RES ,0><<<gE, 256, GSM_BYTES>>>(BT, E, E, py, pWpT + wOff, bp + l*E, ph, ph);
        ln_kernel<<<BT, 256>>>(ph, pxn, ln2_g + l*E, ln2_b + l*E);
        gemm_mma<EPI_GELU,1><<<gF, 256, GSM_BYTES>>>(BT, FF, E, pxn, pWf1T + f1Off, bf1 + (size_t)l*FF, nullptr, pff);
        gemm_mma<EPI_RES ,0><<<gE, 256, GSM_BYTES>>>(BT, E, FF, pff, pWf2T + f1Off, bf2 + l*E, ph, ph);
    }

    ln_kernel<<<BT, 256>>>(ph, pxn, lnf_g, lnf_b);
    gemm_mma<EPI_BIAS,0><<<gV, 256, GSM_BYTES>>>(BT, VOCAB, E, pxn, pHT, nullptr, nullptr, out);
}

// round 16
// speedup vs baseline: 1.3231x; 1.3231x over previous
#include <cuda_runtime.h>
#include <cuda_fp16.h>
#include <math.h>
#include <stdint.h>

// ---------------- problem constants ----------------
#define LNUM 12
#define E 1024
#define H 16
#define T 512
#define BATCH 8
#define VOCAB 512
#define FF 4096
#define D 64
#define BT (BATCH*T)   // 4096

// ---------------- persistent device scratch ----------------
__device__ float  g_h [BT*E];
__device__ __half g_xn[BT*E];            // half, k-permuted
__device__ __half g_q [BT*E];            // half, D-permuted per head
__device__ __half g_k [BT*E];            // half, D-permuted per head
__device__ __half g_v [BT*E];            // half, plain
__device__ __half g_y [BT*E];            // half, k-permuted
__device__ __half g_ff[(size_t)BT*FF];   // half, k-permuted
// transposed (K-major, k-permuted) fp16 weights
__device__ __half g_WqT [(size_t)LNUM*E*E];
__device__ __half g_WkT [(size_t)LNUM*E*E];
__device__ __half g_WvT [(size_t)LNUM*E*E];
__device__ __half g_WpT [(size_t)LNUM*E*E];
__device__ __half g_Wf1T[(size_t)LNUM*E*FF];
__device__ __half g_Wf2T[(size_t)LNUM*FF*E];
__device__ __half g_headT[(size_t)E*VOCAB];

// ---------------- helpers ----------------
__device__ __forceinline__ uint32_t smem_u32(const void* p) {
    uint32_t a;
    asm("{ .reg .u64 t; cvta.to.shared.u64 t, %1; cvt.u32.u64 %0, t; }" : "=r"(a) : "l"(p));
    return a;
}
__device__ __forceinline__ void cp16(uint32_t saddr, const void* g) {
    asm volatile("cp.async.cg.shared.global [%0], [%1], 16;" :: "r"(saddr), "l"(g));
}
__device__ __forceinline__ void cp_commit() {
    asm volatile("cp.async.commit_group;" ::: "memory");
}
template<int N>
__device__ __forceinline__ void cp_wait() {
    asm volatile("cp.async.wait_group %0;" :: "n"(N) : "memory");
}
__device__ __forceinline__ void mma_f16(float* d, uint32_t a0, uint32_t a1, uint32_t a2,
                                        uint32_t a3, uint32_t b0, uint32_t b1) {
    asm volatile("mma.sync.aligned.m16n8k16.row.col.f32.f16.f16.f32 "
        "{%0,%1,%2,%3}, {%4,%5,%6,%7}, {%8,%9}, {%0,%1,%2,%3};"
        : "+f"(d[0]), "+f"(d[1]), "+f"(d[2]), "+f"(d[3])
        : "r"(a0), "r"(a1), "r"(a2), "r"(a3), "r"(b0), "r"(b1));
}
__device__ __forceinline__ int perm8(int w) {
    return (w & ~7) | ((w & 3) << 1) | ((w >> 2) & 1);
}
__device__ __forceinline__ int permh(int k) {
    return perm8(k >> 1) * 2 + (k & 1);
}

// ---------------- embedding ----------------
__global__ void embed_kernel(const int* __restrict__ x,
                             const float* __restrict__ tok,
                             const float* __restrict__ pos,
                             float* __restrict__ h)
{
    int idx = blockIdx.x * blockDim.x + threadIdx.x;
    if (idx >= BT*E) return;
    int row = idx >> 10;
    int e   = idx & (E-1);
    int t   = row & (T-1);
    h[idx] = tok[(size_t)x[row]*E + e] + pos[(size_t)t*E + e];
}

// ---------------- layernorm (fp16 k-permuted output) ----------------
__global__ __launch_bounds__(256) void ln_kernel(const float* __restrict__ in,
                                                 __half* __restrict__ out,
                                                 const float* __restrict__ gamma,
                                                 const float* __restrict__ beta)
{
    int row = blockIdx.x;
    const float* xr = in + (size_t)row * E;
    float s = 0.f, ss = 0.f;
    for (int i = threadIdx.x; i < E; i += 256) {
        float v = xr[i]; s += v; ss += v * v;
    }
    #pragma unroll
    for (int o = 16; o > 0; o >>= 1) {
        s  += __shfl_xor_sync(0xffffffffu, s,  o);
        ss += __shfl_xor_sync(0xffffffffu, ss, o);
    }
    __shared__ float sred[8], ssred[8];
    int w = threadIdx.x >> 5;
    if ((threadIdx.x & 31) == 0) { sred[w] = s; ssred[w] = ss; }
    __syncthreads();
    if (threadIdx.x < 32) {
        s  = (threadIdx.x < 8) ? sred [threadIdx.x] : 0.f;
        ss = (threadIdx.x < 8) ? ssred[threadIdx.x] : 0.f;
        #pragma unroll
        for (int o = 4; o > 0; o >>= 1) {
            s  += __shfl_xor_sync(0xffffffffu, s,  o);
            ss += __shfl_xor_sync(0xffffffffu, ss, o);
        }
        if (threadIdx.x == 0) { sred[0] = s; ssred[0] = ss; }
    }
    __syncthreads();
    float mu   = sred[0] * (1.f / E);
    float var  = ssred[0] * (1.f / E) - mu * mu;
    float rstd = rsqrtf(var + 1e-5f);
    __half* orow = out + (size_t)row * E;
    for (int i = threadIdx.x; i < E; i += 256)
        orow[permh(i)] = __float2half_rn((xr[i] - mu) * rstd * gamma[i] + beta[i]);
}

// ---------------- weight transpose ([R,C] fp32 -> [C,R] fp16, k-permuted) --------
__global__ __launch_bounds__(256) void transpose_h(const float* __restrict__ in,
                                                   __half* __restrict__ out, int R, int C)
{
    __shared__ float tile[32][33];
    size_t mat = (size_t)blockIdx.z * R * C;
    int c0 = blockIdx.x * 32, r0 = blockIdx.y * 32;
    #pragma unroll
    for (int j = threadIdx.y; j < 32; j += 8)
        tile[j][threadIdx.x] = in[mat + (size_t)(r0 + j) * C + c0 + threadIdx.x];
    __syncthreads();
    int pk = r0 + permh((int)threadIdx.x);
    #pragma unroll
    for (int j = threadIdx.y; j < 32; j += 8)
        out[mat + (size_t)(c0 + j) * R + pk] = __float2half_rn(tile[threadIdx.x][j]);
}

// ---------------- fp16 mma GEMM (256x128 tile, 256 thr, warp 64x64, pipelined) ----
// OUT: 0 = fp32 plain, 1 = fp16 k-permuted, 2 = fp16 plain
#define EPI_BIAS 0
#define EPI_GELU 1
#define EPI_RES  2
#define TKh 64
#define ROWW 40
#define STG_AW (256*ROWW)
#define STG_BW (128*ROWW)
#define STG_W  (STG_AW+STG_BW)
#define STG_B  (STG_W*4)              // 61440 bytes/stage
#define GSM_BYTES (3*STG_B)           // 184320 bytes

// shared mainloop: accumulates C tile (m0, n0) of A[M,K] @ Bt[:,K]^T
__device__ __forceinline__ void gemm_mainloop(
    uint32_t* smw, uint32_t sbase, const __half* A, const __half* Bt,
    size_t m0, int n0, int K, int nK, int tid, int wm, int wn, int g, int c,
    float acc[4][8][4])
{
    const int ldrow = tid >> 3, ldch = tid & 7;

    auto load_tiles = [&](int kt, int st) {
        const int k0 = kt * TKh;
        const uint32_t sA = sbase + st*STG_B;
        const uint32_t sB = sA + STG_AW*4;
        const __half* Ag = A  + (m0 + ldrow) * K + k0 + ldch*8;
        #pragma unroll
        for (int i = 0; i < 8; i++)
            cp16(sA + (ldrow + i*32)*160 + ldch*16, Ag + (size_t)(i*32) * K);
        const __half* Bg = Bt + (size_t)(n0 + ldrow) * K + k0 + ldch*8;
        #pragma unroll
        for (int i = 0; i < 4; i++)
            cp16(sB + (ldrow + i*32)*160 + ldch*16, Bg + (size_t)(i*32) * K);
        cp_commit();
    };

    load_tiles(0, 0);
    load_tiles(1, 1);

    for (int kt = 0; kt < nK; kt++) {
        const int st = kt % 3;
        if (kt < nK - 1) cp_wait<1>(); else cp_wait<0>();
        __syncthreads();
        if (kt + 2 < nK) load_tiles(kt + 2, (kt + 2) % 3);

        const uint32_t* as = smw + st*STG_W;
        const uint32_t* bs = as + STG_AW;

        uint2 af[2][8], bf[2][8];
        {
            const int kw = 2*c;
            #pragma unroll
            for (int mf = 0; mf < 4; mf++) {
                int r = wm*64 + mf*16 + g;
                af[0][2*mf]   = *(const uint2*)&as[ r      * ROWW + kw];
                af[0][2*mf+1] = *(const uint2*)&as[(r + 8) * ROWW + kw];
            }
            #pragma unroll
            for (int nf = 0; nf < 8; nf++)
                bf[0][nf] = *(const uint2*)&bs[(wn*64 + nf*8 + g) * ROWW + kw];
        }
        #pragma unroll
        for (int ks = 0; ks < 4; ks++) {
            const int cur = ks & 1, nxt = cur ^ 1;
            if (ks < 3) {
                const int kw = (ks + 1)*8 + 2*c;
                #pragma unroll
                for (int mf = 0; mf < 4; mf++) {
                    int r = wm*64 + mf*16 + g;
                    af[nxt][2*mf]   = *(const uint2*)&as[ r      * ROWW + kw];
                    af[nxt][2*mf+1] = *(const uint2*)&as[(r + 8) * ROWW + kw];
                }
                #pragma unroll
                for (int nf = 0; nf < 8; nf++)
                    bf[nxt][nf] = *(const uint2*)&bs[(wn*64 + nf*8 + g) * ROWW + kw];
            }
            #pragma unroll
            for (int mf = 0; mf < 4; mf++)
                #pragma unroll
                for (int nf = 0; nf < 8; nf++)
                    mma_f16(acc[mf][nf],
                            af[cur][2*mf].x, af[cur][2*mf+1].x,
                            af[cur][2*mf].y, af[cur][2*mf+1].y,
                            bf[cur][nf].x, bf[cur][nf].y);
        }
        // no trailing sync — loads are issued after the top-of-iteration barrier,
        // and the stage they write was last read one iteration earlier.
    }
}

template<int EPI, int OUT>
__global__ __launch_bounds__(256) void gemm_mma(int M, int N, int K,
    const __half* __restrict__ A, const __half* __restrict__ Bt,
    const float* __restrict__ bias, const float* __restrict__ res,
    void* __restrict__ Cv)
{
    extern __shared__ uint32_t smw[];
    const uint32_t sbase = smem_u32(smw);
    const int tid  = threadIdx.x;
    const int wid  = tid >> 5, lane = tid & 31;
    const int wm   = wid & 3, wn = wid >> 2;
    const int g    = lane >> 2, c = lane & 3;

    const size_t m0 = (size_t)blockIdx.y * 256;
    const int    n0 = blockIdx.x * 128;
    const int    nK = K / TKh;

    float acc[4][8][4];
    #pragma unroll
    for (int mf = 0; mf < 4; mf++)
        #pragma unroll
        for (int nf = 0; nf < 8; nf++)
            #pragma unroll
            for (int i = 0; i < 4; i++) acc[mf][nf][i] = 0.f;

    gemm_mainloop(smw, sbase, A, Bt, m0, n0, K, nK, tid, wm, wn, g, c, acc);

    #pragma unroll
    for (int mf = 0; mf < 4; mf++) {
        size_t r = m0 + wm*64 + mf*16 + g;
        #pragma unroll
        for (int nf = 0; nf < 8; nf++) {
            int col = n0 + wn*64 + nf*8 + c*2;
            float v0 = acc[mf][nf][0], v1 = acc[mf][nf][1];
            float v2 = acc[mf][nf][2], v3 = acc[mf][nf][3];
            if (bias) {
                float bb0 = bias[col], bb1 = bias[col+1];
                v0 += bb0; v1 += bb1; v2 += bb0; v3 += bb1;
            }
            if (EPI == EPI_GELU) {
                v0 = 0.5f*v0*(1.f + erff(v0*0.70710678118654752f));
                v1 = 0.5f*v1*(1.f + erff(v1*0.70710678118654752f));
                v2 = 0.5f*v2*(1.f + erff(v2*0.70710678118654752f));
                v3 = 0.5f*v3*(1.f + erff(v3*0.70710678118654752f));
            }
            if (EPI == EPI_RES) {
                const float* resp = res + r*N + col;
                float2 r0 = *(const float2*)resp;
                float2 r1 = *(const float2*)(resp + 8*N);
                v0 += r0.x; v1 += r0.y; v2 += r1.x; v3 += r1.y;
            }
            if (OUT == 1) {
                __half* C = (__half*)Cv;
                int p0 = permh(col), p1 = permh(col + 1);
                C[r*N + p0]     = __float2half_rn(v0);
                C[r*N + p1]     = __float2half_rn(v1);
                C[(r+8)*N + p0] = __float2half_rn(v2);
                C[(r+8)*N + p1] = __float2half_rn(v3);
            } else if (OUT == 2) {
                __half* C = (__half*)Cv;
                *(__half2*)(C + r*N + col)     = __floats2half2_rn(v0, v1);
                *(__half2*)(C + (r+8)*N + col) = __floats2half2_rn(v2, v3);
            } else {
                float* C = (float*)Cv;
                float2 o0 = {v0, v1}, o1 = {v2, v3};
                *(float2*)(C + r*N + col)     = o0;
                *(float2*)(C + (r+8)*N + col) = o1;
            }
        }
    }
}

// ---------------- fused QKV GEMM: one launch, 384 blocks ----------------
// blockIdx.x: [0,8) -> Q, [8,16) -> K, [16,24) -> V. Same A for all.
__global__ __launch_bounds__(256) void gemm_qkv(
    const __half* __restrict__ A,
    const __half* __restrict__ WqT, const __half* __restrict__ WkT,
    const __half* __restrict__ WvT,
    const float* __restrict__ bq, const float* __restrict__ bk,
    const float* __restrict__ bv,
    __half* __restrict__ Q, __half* __restrict__ K2, __half* __restrict__ V)
{
    extern __shared__ uint32_t smw[];
    const uint32_t sbase = smem_u32(smw);
    const int tid  = threadIdx.x;
    const int wid  = tid >> 5, lane = tid & 31;
    const int wm   = wid & 3, wn = wid >> 2;
    const int g    = lane >> 2, c = lane & 3;

    const int bx = blockIdx.x;
    const __half* Bt;
    const float* bias;
    __half* C;
    int n0, plain;
    if (bx < 8)       { Bt = WqT; bias = bq; C = Q;  n0 = bx*128;      plain = 0; }
    else if (bx < 16) { Bt = WkT; bias = bk; C = K2; n0 = (bx-8)*128;  plain = 0; }
    else              { Bt = WvT; bias = bv; C = V;  n0 = (bx-16)*128; plain = 1; }

    const size_t m0 = (size_t)blockIdx.y * 256;
    const int    nK = E / TKh;

    float acc[4][8][4];
    #pragma unroll
    for (int mf = 0; mf < 4; mf++)
        #pragma unroll
        for (int nf = 0; nf < 8; nf++)
            #pragma unroll
            for (int i = 0; i < 4; i++) acc[mf][nf][i] = 0.f;

    gemm_mainloop(smw, sbase, A, Bt, m0, n0, E, nK, tid, wm, wn, g, c, acc);

    #pragma unroll
    for (int mf = 0; mf < 4; mf++) {
        size_t r = m0 + wm*64 + mf*16 + g;
        #pragma unroll
        for (int nf = 0; nf < 8; nf++) {
            int col = n0 + wn*64 + nf*8 + c*2;
            float bb0 = bias[col], bb1 = bias[col+1];
            float v0 = acc[mf][nf][0] + bb0, v1 = acc[mf][nf][1] + bb1;
            float v2 = acc[mf][nf][2] + bb0, v3 = acc[mf][nf][3] + bb1;
            if (plain) {
                *(__half2*)(C + r*E + col)     = __floats2half2_rn(v0, v1);
                *(__half2*)(C + (r+8)*E + col) = __floats2half2_rn(v2, v3);
            } else {
                int p0 = permh(col), p1 = permh(col + 1);
                C[r*E + p0]     = __float2half_rn(v0);
                C[r*E + p1]     = __float2half_rn(v1);
                C[(r+8)*E + p0] = __float2half_rn(v2);
                C[(r+8)*E + p1] = __float2half_rn(v3);
            }
        }
    }
}

// ---------------- tensor-core flash attention ----------------
__global__ __launch_bounds__(128) void attn_kernel(const __half* __restrict__ Qh,
                                                   const __half* __restrict__ Kh,
                                                   const __half* __restrict__ Vh,
                                                   __half* __restrict__ Y)
{
    __shared__ __align__(16) uint32_t sQ[64*ROWW];
    __shared__ __align__(16) uint32_t sK[64*ROWW];
    __shared__ __align__(16) uint32_t sVt[64*ROWW];

    const int bh = blockIdx.y;
    const int b  = bh >> 4;
    const int h  = bh & 15;
    const int qt = blockIdx.x;
    const int tid  = threadIdx.x;
    const int wid  = tid >> 5, lane = tid & 31;
    const int g    = lane >> 2, c = lane & 3;

    {
        int r2 = tid >> 1, wc = tid & 1;
        const uint4* qg = (const uint4*)(Qh + (size_t)(b*T + qt*64 + r2)*E + h*64 + wc*32);
        uint4* sq4 = (uint4*)(sQ + r2*ROWW + wc*16);
        sq4[0] = qg[0]; sq4[1] = qg[1]; sq4[2] = qg[2]; sq4[3] = qg[3];
    }
    __syncthreads();

    uint2 aq[4][2];
    {
        int qr = wid*16 + g;
        #pragma unroll
        for (int ks = 0; ks < 4; ks++) {
            aq[ks][0] = *(const uint2*)&sQ[ qr      * ROWW + ks*8 + 2*c];
            aq[ks][1] = *(const uint2*)&sQ[(qr + 8) * ROWW + ks*8 + 2*c];
        }
    }

    float o[8][4];
    #pragma unroll
    for (int dt = 0; dt < 8; dt++)
        #pragma unroll
        for (int i = 0; i < 4; i++) o[dt][i] = 0.f;
    float m0 = -INFINITY, m1 = -INFINITY, l0 = 0.f, l1 = 0.f;

    for (int kt = 0; kt <= qt; kt++) {
        __syncthreads();
        {
            int r2 = tid >> 1, wc = tid & 1;
            const uint4* kg = (const uint4*)(Kh + (size_t)(b*T + kt*64 + r2)*E + h*64 + wc*32);
            uint4* sk4 = (uint4*)(sK + r2*ROWW + wc*16);
            sk4[0] = kg[0]; sk4[1] = kg[1]; sk4[2] = kg[2]; sk4[3] = kg[3];
        }
        {
            int key = tid >> 1, dbase = (tid & 1) * 32;
            const uint4* vg = (const uint4*)(Vh + (size_t)(b*T + kt*64 + key)*E + h*64 + dbase);
            __half* vt = (__half*)sVt;
            int pk = permh(key);
            #pragma unroll
            for (int j = 0; j < 4; j++) {
                uint4 v = vg[j];
                const __half* hh = (const __half*)&v;
                #pragma unroll
                for (int i = 0; i < 8; i++)
                    vt[(dbase + j*8 + i)*(2*ROWW) + pk] = hh[i];
            }
        }
        __syncthreads();

        float s[8][4];
        #pragma unroll
        for (int nt = 0; nt < 8; nt++) {
            s[nt][0] = s[nt][1] = s[nt][2] = s[nt][3] = 0.f;
            #pragma unroll
            for (int ks = 0; ks < 4; ks++) {
                uint2 bk = *(const uint2*)&sK[(nt*8 + g) * ROWW + ks*8 + 2*c];
                mma_f16(s[nt], aq[ks][0].x, aq[ks][1].x, aq[ks][0].y, aq[ks][1].y,
                        bk.x, bk.y);
            }
        }

        const int wr0 = wid*16 + g, wr1 = wr0 + 8;
        float mx0 = -INFINITY, mx1 = -INFINITY;
        #pragma unroll
        for (int nt = 0; nt < 8; nt++) {
            #pragma unroll
            for (int i = 0; i < 4; i++) s[nt][i] *= 0.125f;
            if (kt == qt) {
                int cl = nt*8 + 2*c;
                if (cl     > wr0) s[nt][0] = -INFINITY;
                if (cl + 1 > wr0) s[nt][1] = -INFINITY;
                if (cl     > wr1) s[nt][2] = -INFINITY;
                if (cl + 1 > wr1) s[nt][3] = -INFINITY;
            }
            mx0 = fmaxf(mx0, fmaxf(s[nt][0], s[nt][1]));
            mx1 = fmaxf(mx1, fmaxf(s[nt][2], s[nt][3]));
        }
        mx0 = fmaxf(mx0, __shfl_xor_sync(0xffffffffu, mx0, 1));
        mx0 = fmaxf(mx0, __shfl_xor_sync(0xffffffffu, mx0, 2));
        mx1 = fmaxf(mx1, __shfl_xor_sync(0xffffffffu, mx1, 1));
        mx1 = fmaxf(mx1, __shfl_xor_sync(0xffffffffu, mx1, 2));

        float nm0 = fmaxf(m0, mx0), nm1 = fmaxf(m1, mx1);
        float f0 = __expf(m0 - nm0), f1 = __expf(m1 - nm1);
        m0 = nm0; m1 = nm1;

        float sum0 = 0.f, sum1 = 0.f;
        uint32_t ph[8][2];
        #pragma unroll
        for (int nt = 0; nt < 8; nt++) {
            float p0 = __expf(s[nt][0] - m0);
            float p1 = __expf(s[nt][1] - m0);
            float p2 = __expf(s[nt][2] - m1);
            float p3 = __expf(s[nt][3] - m1);
            sum0 += p0 + p1; sum1 += p2 + p3;
            __half2 h01 = __floats2half2_rn(p0, p1);
            __half2 h23 = __floats2half2_rn(p2, p3);
            ph[nt][0] = *(uint32_t*)&h01;
            ph[nt][1] = *(uint32_t*)&h23;
        }
        sum0 += __shfl_xor_sync(0xffffffffu, sum0, 1);
        sum0 += __shfl_xor_sync(0xffffffffu, sum0, 2);
        sum1 += __shfl_xor_sync(0xffffffffu, sum1, 1);
        sum1 += __shfl_xor_sync(0xffffffffu, sum1, 2);
        l0 = l0*f0 + sum0;
        l1 = l1*f1 + sum1;

        #pragma unroll
        for (int dt = 0; dt < 8; dt++) {
            o[dt][0] *= f0; o[dt][1] *= f0;
            o[dt][2] *= f1; o[dt][3] *= f1;
            #pragma unroll
            for (int kp = 0; kp < 4; kp++) {
                uint2 bv = *(const uint2*)&sVt[(dt*8 + g) * ROWW + kp*8 + 2*c];
                mma_f16(o[dt], ph[2*kp][0], ph[2*kp][1], ph[2*kp+1][0], ph[2*kp+1][1],
                        bv.x, bv.y);
            }
        }
    }

    float i0 = 1.f / l0, i1 = 1.f / l1;
    size_t row0 = (size_t)(b*T + qt*64 + wid*16 + g);
    size_t row1 = row0 + 8;
    #pragma unroll
    for (int dt = 0; dt < 8; dt++) {
        int gw = h*32 + dt*4 + c;
        int pw = perm8(gw);
        *(__half2*)(Y + row0*E + pw*2) = __floats2half2_rn(o[dt][0]*i0, o[dt][1]*i0);
        *(__half2*)(Y + row1*E + pw*2) = __floats2half2_rn(o[dt][2]*i1, o[dt][3]*i1);
    }
}

// ---------------- host orchestration ----------------
extern "C" void kernel_launch(void* const* d_in, const int* in_sizes, int n_in,
                              void* d_out, int out_size)
{
    (void)in_sizes; (void)n_in; (void)out_size;
    const int*   x     = (const int*)  d_in[0];
    const float* tok   = (const float*)d_in[2];
    const float* pos   = (const float*)d_in[3];
    const float* ln1_g = (const float*)d_in[4];
    const float* ln1_b = (const float*)d_in[5];
    const float* Wq    = (const float*)d_in[6];
    const float* bq    = (const float*)d_in[7];
    const float* Wk    = (const float*)d_in[8];
    const float* bk    = (const float*)d_in[9];
    const float* Wv    = (const float*)d_in[10];
    const float* bv    = (const float*)d_in[11];
    const float* Wp    = (const float*)d_in[12];
    const float* bp    = (const float*)d_in[13];
    const float* ln2_g = (const float*)d_in[14];
    const float* ln2_b = (const float*)d_in[15];
    const float* Wf1   = (const float*)d_in[16];
    const float* bf1   = (const float*)d_in[17];
    const float* Wf2   = (const float*)d_in[18];
    const float* bf2   = (const float*)d_in[19];
    const float* lnf_g = (const float*)d_in[20];
    const float* lnf_b = (const float*)d_in[21];
    const float* headw = (const float*)d_in[22];
    float* out = (float*)d_out;

    float *ph;
    __half *pxn, *pq, *pk, *pv, *py, *pff;
    __half *pWqT, *pWkT, *pWvT, *pWpT, *pWf1T, *pWf2T, *pHT;
    cudaGetSymbolAddress((void**)&ph,   g_h);
    cudaGetSymbolAddress((void**)&pxn,  g_xn);
    cudaGetSymbolAddress((void**)&pq,   g_q);
    cudaGetSymbolAddress((void**)&pk,   g_k);
    cudaGetSymbolAddress((void**)&pv,   g_v);
    cudaGetSymbolAddress((void**)&py,   g_y);
    cudaGetSymbolAddress((void**)&pff,  g_ff);
    cudaGetSymbolAddress((void**)&pWqT, g_WqT);
    cudaGetSymbolAddress((void**)&pWkT, g_WkT);
    cudaGetSymbolAddress((void**)&pWvT, g_WvT);
    cudaGetSymbolAddress((void**)&pWpT, g_WpT);
    cudaGetSymbolAddress((void**)&pWf1T, g_Wf1T);
    cudaGetSymbolAddress((void**)&pWf2T, g_Wf2T);
    cudaGetSymbolAddress((void**)&pHT,  g_headT);

    cudaFuncSetAttribute(gemm_qkv,               cudaFuncAttributeMaxDynamicSharedMemorySize, GSM_BYTES);
    cudaFuncSetAttribute(gemm_mma<EPI_BIAS,0>,   cudaFuncAttributeMaxDynamicSharedMemorySize, GSM_BYTES);
    cudaFuncSetAttribute(gemm_mma<EPI_GELU,1>,   cudaFuncAttributeMaxDynamicSharedMemorySize, GSM_BYTES);
    cudaFuncSetAttribute(gemm_mma<EPI_RES ,0>,   cudaFuncAttributeMaxDynamicSharedMemorySize, GSM_BYTES);

    dim3 tb(32, 8);
    dim3 gQKV(24,      BT/256);   // (24,16) = 384 blocks
    dim3 gE(E/128,     BT/256);   // (8,16)
    dim3 gF(FF/128,    BT/256);   // (32,16)
    dim3 gV(VOCAB/128, BT/256);   // (4,16)
    dim3 gAtt(T/64, BATCH*H);

    transpose_h<<<dim3(E/32, E/32, LNUM), tb>>>(Wq, pWqT, E, E);            // 0
    embed_kernel<<<(BT*E + 255)/256, 256>>>(x, tok, pos, ph);               // 1
    transpose_h<<<dim3(E/32,  E/32,  LNUM), tb>>>(Wk,  pWkT,  E,  E);       // 2
    transpose_h<<<dim3(E/32,  E/32,  LNUM), tb>>>(Wv,  pWvT,  E,  E);       // 3
    transpose_h<<<dim3(E/32,  E/32,  LNUM), tb>>>(Wp,  pWpT,  E,  E);
    transpose_h<<<dim3(FF/32, E/32,  LNUM), tb>>>(Wf1, pWf1T, E,  FF);
    transpose_h<<<dim3(E/32,  FF/32, LNUM), tb>>>(Wf2, pWf2T, FF, E);
    transpose_h<<<dim3(VOCAB/32, E/32, 1),  tb>>>(headw, pHT, E,  VOCAB);

    for (int l = 0; l < LNUM; l++) {
        const size_t wOff  = (size_t)l * E * E;
        const size_t f1Off = (size_t)l * E * FF;
        ln_kernel<<<BT, 256>>>(ph, pxn, ln1_g + l*E, ln1_b + l*E);
        gemm_qkv<<<gQKV, 256, GSM_BYTES>>>(pxn, pWqT + wOff, pWkT + wOff, pWvT + wOff,
                                           bq + l*E, bk + l*E, bv + l*E, pq, pk, pv);
        attn_kernel<<<gAtt, 128>>>(pq, pk, pv, py);
        gemm_mma<EPI_RES ,0><<<gE, 256, GSM_BYTES>>>(BT, E, E, py, pWpT + wOff, bp + l*E, ph, ph);
        ln_kernel<<<BT, 256>>>(ph, pxn, ln2_g + l*E, ln2_b + l*E);
        gemm_mma<EPI_GELU,1><<<gF, 256, GSM_BYTES>>>(BT, FF, E, pxn, pWf1T + f1Off, bf1 + (size_t)l*FF, nullptr, pff);
        gemm_mma<EPI_RES ,0><<<gE, 256, GSM_BYTES>>>(BT, E, FF, pff, pWf2T + f1Off, bf2 + l*E, ph, ph);
    }

    ln_kernel<<<BT, 256>>>(ph, pxn, lnf_g, lnf_b);
    gemm_mma<EPI_BIAS,0><<<gV, 256, GSM_BYTES>>>(BT, VOCAB, E, pxn, pHT, nullptr, nullptr, out);
}